// round 1
// baseline (speedup 1.0000x reference)
#include <cuda_runtime.h>
#include <cuda_bf16.h>
#include <math.h>

#define IN_F   256
#define OUT_F  256
#define N_E    10000
#define N_KC   2000
#define ALPHA  0.2f

// ---------------- scratch (static __device__, no allocation) ----------------
__device__ float g_kcWh[N_KC * OUT_F];     // 2 MB
__device__ float g_exEh[N_E * OUT_F];      // 10 MB
__device__ float g_feat[N_E * 2 * OUT_F];  // 20 MB
__device__ float g_e1[N_E];
__device__ float g_e2[N_KC];
__device__ float g_v1[IN_F];
__device__ float g_v2[IN_F];
__device__ float g_rdT[2 * OUT_F * OUT_F]; // rd_w transposed: [512][256]

// ---------------- prep: v1 = W1@a1, v2 = W1@a2, rdT = rd_w^T ----------------
__global__ void prep_kernel(const float* __restrict__ W1, const float* __restrict__ a,
                            const float* __restrict__ rd_w)
{
    int b = blockIdx.x;
    if (b == 0) {
        int k = threadIdx.x; // 0..255
        float s1 = 0.f, s2 = 0.f;
        #pragma unroll 8
        for (int j = 0; j < OUT_F; j++) {
            float w = W1[k * OUT_F + j];
            s1 += w * a[j];
            s2 += w * a[OUT_F + j];
        }
        g_v1[k] = s1;
        g_v2[k] = s2;
    } else {
        int idx = (b - 1) * 256 + threadIdx.x;
        if (idx < 2 * OUT_F * OUT_F) {
            int k = idx >> 8;       // 0..511
            int n = idx & 255;      // 0..255
            g_rdT[idx] = rd_w[n * (2 * OUT_F) + k];
        }
    }
}

// ---------------- row dot: out[i] = dot(X[i,:256], v) ----------------
__global__ void rowdot_kernel(const float* __restrict__ X, const float* __restrict__ v,
                              float* __restrict__ out, int M)
{
    int gwarp = (blockIdx.x * blockDim.x + threadIdx.x) >> 5;
    int lane = threadIdx.x & 31;
    if (gwarp >= M) return;
    const float* row = X + (size_t)gwarp * IN_F;
    float s = 0.f;
    #pragma unroll
    for (int k = lane; k < IN_F; k += 32) s += row[k] * v[k];
    #pragma unroll
    for (int o = 16; o; o >>= 1) s += __shfl_xor_sync(0xFFFFFFFFu, s, o);
    if (lane == 0) out[gwarp] = s;
}

// ---------------- tiled SGEMM: C[M,N] = A[M,K] @ B[K,N] ----------------
// BM=128, BN=64, BK=16, per-thread 8x4. N % 64 == 0, K % 16 == 0 assumed.
// epi==1: C = elu(C + bias)
#define GBM 128
#define GBN 64
#define GBK 16
__global__ __launch_bounds__(256) void sgemm_kernel(
    const float* __restrict__ A, const float* __restrict__ B, float* __restrict__ C,
    int M, int N, int K, const float* __restrict__ bias, int epi)
{
    __shared__ float As[GBK][GBM];
    __shared__ float Bs[GBK][GBN];
    int tid = threadIdx.x;
    int bm = blockIdx.y * GBM;
    int bn = blockIdx.x * GBN;
    int tx = tid & 15;          // 0..15 -> 4 cols
    int ty = tid >> 4;          // 0..15 -> 8 rows
    float acc[8][4];
    #pragma unroll
    for (int m = 0; m < 8; m++)
        #pragma unroll
        for (int n = 0; n < 4; n++) acc[m][n] = 0.f;

    int brow = tid >> 4;          // 0..15
    int bcol = (tid & 15) * 4;    // 0..60

    for (int k0 = 0; k0 < K; k0 += GBK) {
        // load A tile 128x16 (2 float4 per thread)
        #pragma unroll
        for (int l = 0; l < 2; l++) {
            int f = tid + l * 256;        // 0..511 float4 id
            int row = f >> 2;             // 0..127
            int col = (f & 3) * 4;        // 0,4,8,12
            float4 av;
            if (bm + row < M)
                av = *(const float4*)&A[(size_t)(bm + row) * K + k0 + col];
            else
                av = make_float4(0.f, 0.f, 0.f, 0.f);
            As[col + 0][row] = av.x;
            As[col + 1][row] = av.y;
            As[col + 2][row] = av.z;
            As[col + 3][row] = av.w;
        }
        // load B tile 16x64 (1 float4 per thread)
        *(float4*)&Bs[brow][bcol] = *(const float4*)&B[(size_t)(k0 + brow) * N + bn + bcol];
        __syncthreads();
        #pragma unroll
        for (int k = 0; k < GBK; k++) {
            float4 a0 = *(const float4*)&As[k][ty * 8];
            float4 a1 = *(const float4*)&As[k][ty * 8 + 4];
            float4 b0 = *(const float4*)&Bs[k][tx * 4];
            float ar[8] = {a0.x, a0.y, a0.z, a0.w, a1.x, a1.y, a1.z, a1.w};
            float br[4] = {b0.x, b0.y, b0.z, b0.w};
            #pragma unroll
            for (int m = 0; m < 8; m++)
                #pragma unroll
                for (int n = 0; n < 4; n++)
                    acc[m][n] = fmaf(ar[m], br[n], acc[m][n]);
        }
        __syncthreads();
    }
    #pragma unroll
    for (int m = 0; m < 8; m++) {
        int row = bm + ty * 8 + m;
        if (row >= M) continue;
        #pragma unroll
        for (int n = 0; n < 4; n++) {
            int col = bn + tx * 4 + n;
            float v = acc[m][n];
            if (epi == 1) {
                v += bias[col];
                v = v > 0.f ? v : expm1f(v);
            }
            C[(size_t)row * N + col] = v;
        }
    }
}

// ---------------- fused masked-softmax attention + aggregation ----------------
// 8 exercise rows per block, 256 threads. Writes new_kc and new_kc*exEh into feat.
#define ROWS 8
#define NCH  8   // ceil(2000/256)
__global__ __launch_bounds__(256) void attn_kernel(
    const float* __restrict__ e1, const float* __restrict__ e2,
    const int* __restrict__ adj, const float* __restrict__ kcWh,
    const float* __restrict__ exEh, float* __restrict__ feat)
{
    __shared__ float e2s[N_KC];
    __shared__ unsigned maskb[ROWS][64];
    __shared__ float pbuf[ROWS][256];
    __shared__ float red[8];
    __shared__ float rmax_s[ROWS];
    __shared__ float rinv_s[ROWS];
    __shared__ float e1s[ROWS];

    int tid  = threadIdx.x;
    int lane = tid & 31;
    int warp = tid >> 5;
    int i0 = blockIdx.x * ROWS;

    for (int j = tid; j < N_KC; j += 256) e2s[j] = e2[j];
    if (tid < ROWS) e1s[tid] = e1[i0 + tid];
    __syncthreads();

    // ----- per-row softmax stats + adjacency bit-pack -----
    for (int i = 0; i < ROWS; i++) {
        float e1i = e1s[i];
        const int* arow = adj + (size_t)(i0 + i) * N_KC;
        float lmax = -INFINITY;
        #pragma unroll
        for (int it = 0; it < NCH; it++) {
            int j = tid + it * 256;
            int av = (j < N_KC) ? arow[j] : 0;
            unsigned bal = __ballot_sync(0xFFFFFFFFu, av > 0);
            if (lane == 0) maskb[i][warp + it * 8] = bal;
            if (av > 0) {
                float v = e1i + e2s[j];
                v = v > 0.f ? v : ALPHA * v;
                lmax = fmaxf(lmax, v);
            }
        }
        #pragma unroll
        for (int o = 16; o; o >>= 1) lmax = fmaxf(lmax, __shfl_xor_sync(0xFFFFFFFFu, lmax, o));
        if (lane == 0) red[warp] = lmax;
        __syncthreads();
        if (warp == 0) {
            float m = (lane < 8) ? red[lane] : -INFINITY;
            #pragma unroll
            for (int o = 4; o; o >>= 1) m = fmaxf(m, __shfl_xor_sync(0xFFFFFFFFu, m, o));
            if (lane == 0) red[0] = m;
        }
        __syncthreads();
        float rmax = red[0];
        __syncthreads();

        float lsum = 0.f;
        if (rmax > -INFINITY) {
            #pragma unroll
            for (int it = 0; it < NCH; it++) {
                int j = tid + it * 256;
                if (j < N_KC) {
                    unsigned bit = (maskb[i][j >> 5] >> (j & 31)) & 1u;
                    if (bit) {
                        float v = e1i + e2s[j];
                        v = v > 0.f ? v : ALPHA * v;
                        lsum += __expf(v - rmax);
                    }
                }
            }
        }
        #pragma unroll
        for (int o = 16; o; o >>= 1) lsum += __shfl_xor_sync(0xFFFFFFFFu, lsum, o);
        if (lane == 0) red[warp] = lsum;
        __syncthreads();
        if (warp == 0 && lane == 0) {
            float s = 0.f;
            for (int w = 0; w < 8; w++) s += red[w];
            rmax_s[i] = rmax;
            // degenerate row (no edges): reference softmax is uniform 1/N_KC
            rinv_s[i] = (rmax > -INFINITY) ? 1.0f / s : -1.0f;
        }
        __syncthreads();
    }

    // ----- aggregation: acc[i] = sum_j p_ij * kcWh[j, tid] -----
    float acc[ROWS];
    #pragma unroll
    for (int i = 0; i < ROWS; i++) acc[i] = 0.f;

    for (int c = 0; c < NCH; c++) {
        int j0 = c * 256;
        int j = j0 + tid;
        if (j < N_KC) {
            float e2j = e2s[j];
            #pragma unroll
            for (int i = 0; i < ROWS; i++) {
                float rinv = rinv_s[i];
                float p;
                if (rinv < 0.f) {
                    p = 1.0f / N_KC;
                } else {
                    unsigned bit = (maskb[i][j >> 5] >> (j & 31)) & 1u;
                    float v = e1s[i] + e2j;
                    v = v > 0.f ? v : ALPHA * v;
                    p = bit ? __expf(v - rmax_s[i]) * rinv : 0.f;
                }
                pbuf[i][tid] = p;
            }
        } else {
            #pragma unroll
            for (int i = 0; i < ROWS; i++) pbuf[i][tid] = 0.f;
        }
        __syncthreads();
        int lim = min(256, N_KC - j0);   // 256 or 208; both % 4 == 0
        for (int jj = 0; jj < lim; jj += 4) {
            float w0 = kcWh[(size_t)(j0 + jj + 0) * OUT_F + tid];
            float w1 = kcWh[(size_t)(j0 + jj + 1) * OUT_F + tid];
            float w2 = kcWh[(size_t)(j0 + jj + 2) * OUT_F + tid];
            float w3 = kcWh[(size_t)(j0 + jj + 3) * OUT_F + tid];
            #pragma unroll
            for (int i = 0; i < ROWS; i++) {
                float4 p4 = *(const float4*)&pbuf[i][jj];
                acc[i] = fmaf(p4.x, w0, acc[i]);
                acc[i] = fmaf(p4.y, w1, acc[i]);
                acc[i] = fmaf(p4.z, w2, acc[i]);
                acc[i] = fmaf(p4.w, w3, acc[i]);
            }
        }
        __syncthreads();
    }

    #pragma unroll
    for (int i = 0; i < ROWS; i++) {
        int gi = i0 + i;
        float nk = acc[i];
        feat[(size_t)gi * (2 * OUT_F) + tid]          = nk;
        feat[(size_t)gi * (2 * OUT_F) + OUT_F + tid]  = nk * exEh[(size_t)gi * OUT_F + tid];
    }
}

// ---------------- launch ----------------
extern "C" void kernel_launch(void* const* d_in, const int* in_sizes, int n_in,
                              void* d_out, int out_size)
{
    const float* ex   = (const float*)d_in[0];
    const float* kc   = (const float*)d_in[1];
    const int*   adj  = (const int*)d_in[2];
    const float* W1   = (const float*)d_in[3];
    const float* E    = (const float*)d_in[4];
    const float* a    = (const float*)d_in[5];
    const float* rd_w = (const float*)d_in[6];
    const float* rd_b = (const float*)d_in[7];
    float* out = (float*)d_out;

    float *kcWh, *exEh, *feat, *e1, *e2, *v1, *v2, *rdT;
    cudaGetSymbolAddress((void**)&kcWh, g_kcWh);
    cudaGetSymbolAddress((void**)&exEh, g_exEh);
    cudaGetSymbolAddress((void**)&feat, g_feat);
    cudaGetSymbolAddress((void**)&e1, g_e1);
    cudaGetSymbolAddress((void**)&e2, g_e2);
    cudaGetSymbolAddress((void**)&v1, g_v1);
    cudaGetSymbolAddress((void**)&v2, g_v2);
    cudaGetSymbolAddress((void**)&rdT, g_rdT);

    // 1. v1, v2, rd_w transpose
    prep_kernel<<<1 + (2 * OUT_F * OUT_F + 255) / 256, 256>>>(W1, a, rd_w);

    // 2. kc_Wh = kc_h @ W1   [2000,256]
    sgemm_kernel<<<dim3(OUT_F / GBN, (N_KC + GBM - 1) / GBM), 256>>>(
        kc, W1, kcWh, N_KC, OUT_F, IN_F, nullptr, 0);

    // 3. e1 = ex @ v1, e2 = kc @ v2
    rowdot_kernel<<<(N_E * 32 + 255) / 256, 256>>>(ex, v1, e1, N_E);
    rowdot_kernel<<<(N_KC * 32 + 255) / 256, 256>>>(kc, v2, e2, N_KC);

    // 4. ex_Eh = ex @ E   [10000,256]
    sgemm_kernel<<<dim3(OUT_F / GBN, (N_E + GBM - 1) / GBM), 256>>>(
        ex, E, exEh, N_E, OUT_F, IN_F, nullptr, 0);

    // 5. fused attention -> feat [10000, 512]
    attn_kernel<<<N_E / ROWS, 256>>>(e1, e2, adj, kcWh, exEh, feat);

    // 6. out = elu(feat @ rdT + rd_b)   [10000,256]
    sgemm_kernel<<<dim3(OUT_F / GBN, (N_E + GBM - 1) / GBM), 256>>>(
        feat, rdT, out, N_E, OUT_F, 2 * OUT_F, rd_b, 1);
}

// round 2
// speedup vs baseline: 1.0025x; 1.0025x over previous
#include <cuda_runtime.h>
#include <cuda_bf16.h>
#include <math.h>

#define IN_F   256
#define OUT_F  256
#define N_E    10000
#define N_KC   2000
#define ALPHA  0.2f

// ---------------- scratch (static __device__, no allocation) ----------------
__device__ float g_kcWh[N_KC * OUT_F];     // 2 MB
__device__ float g_exEh[N_E * OUT_F];      // 10 MB
__device__ float g_feat[N_E * 2 * OUT_F];  // 20 MB
__device__ float g_e1[N_E];
__device__ float g_e2[N_KC];
__device__ float g_v1[IN_F];
__device__ float g_v2[IN_F];
__device__ float g_rdT[2 * OUT_F * OUT_F]; // rd_w transposed: [512][256]

// ---------------- prep: v1 = W1@a1, v2 = W1@a2, rdT = rd_w^T ----------------
__global__ void prep_kernel(const float* __restrict__ W1, const float* __restrict__ a,
                            const float* __restrict__ rd_w)
{
    int b = blockIdx.x;
    if (b == 0) {
        int k = threadIdx.x; // 0..255
        float s1 = 0.f, s2 = 0.f;
        #pragma unroll 8
        for (int j = 0; j < OUT_F; j++) {
            float w = W1[k * OUT_F + j];
            s1 += w * a[j];
            s2 += w * a[OUT_F + j];
        }
        g_v1[k] = s1;
        g_v2[k] = s2;
    } else {
        int idx = (b - 1) * 256 + threadIdx.x;
        if (idx < 2 * OUT_F * OUT_F) {
            int k = idx >> 8;       // 0..511
            int n = idx & 255;      // 0..255
            g_rdT[idx] = rd_w[n * (2 * OUT_F) + k];
        }
    }
}

// ---------------- row dot: out[i] = dot(X[i,:256], v) ----------------
__global__ void rowdot_kernel(const float* __restrict__ X, const float* __restrict__ v,
                              float* __restrict__ out, int M)
{
    int gwarp = (blockIdx.x * blockDim.x + threadIdx.x) >> 5;
    int lane = threadIdx.x & 31;
    if (gwarp >= M) return;
    const float* row = X + (size_t)gwarp * IN_F;
    float s = 0.f;
    #pragma unroll
    for (int k = lane; k < IN_F; k += 32) s += row[k] * v[k];
    #pragma unroll
    for (int o = 16; o; o >>= 1) s += __shfl_xor_sync(0xFFFFFFFFu, s, o);
    if (lane == 0) out[gwarp] = s;
}

// ---------------- tiled SGEMM: C[M,N] = A[M,K] @ B[K,N] ----------------
// BM=128, BN=64, BK=16, per-thread 8x4. N % 64 == 0, K % 16 == 0 assumed.
// epi==1: C = elu(C + bias)
#define GBM 128
#define GBN 64
#define GBK 16
__global__ __launch_bounds__(256) void sgemm_kernel(
    const float* __restrict__ A, const float* __restrict__ B, float* __restrict__ C,
    int M, int N, int K, const float* __restrict__ bias, int epi)
{
    __shared__ float As[GBK][GBM];
    __shared__ float Bs[GBK][GBN];
    int tid = threadIdx.x;
    int bm = blockIdx.y * GBM;
    int bn = blockIdx.x * GBN;
    int tx = tid & 15;          // 0..15 -> 4 cols
    int ty = tid >> 4;          // 0..15 -> 8 rows
    float acc[8][4];
    #pragma unroll
    for (int m = 0; m < 8; m++)
        #pragma unroll
        for (int n = 0; n < 4; n++) acc[m][n] = 0.f;

    int brow = tid >> 4;          // 0..15
    int bcol = (tid & 15) * 4;    // 0..60

    for (int k0 = 0; k0 < K; k0 += GBK) {
        // load A tile 128x16 (2 float4 per thread)
        #pragma unroll
        for (int l = 0; l < 2; l++) {
            int f = tid + l * 256;        // 0..511 float4 id
            int row = f >> 2;             // 0..127
            int col = (f & 3) * 4;        // 0,4,8,12
            float4 av;
            if (bm + row < M)
                av = *(const float4*)&A[(size_t)(bm + row) * K + k0 + col];
            else
                av = make_float4(0.f, 0.f, 0.f, 0.f);
            As[col + 0][row] = av.x;
            As[col + 1][row] = av.y;
            As[col + 2][row] = av.z;
            As[col + 3][row] = av.w;
        }
        // load B tile 16x64 (1 float4 per thread)
        *(float4*)&Bs[brow][bcol] = *(const float4*)&B[(size_t)(k0 + brow) * N + bn + bcol];
        __syncthreads();
        #pragma unroll
        for (int k = 0; k < GBK; k++) {
            float4 a0 = *(const float4*)&As[k][ty * 8];
            float4 a1 = *(const float4*)&As[k][ty * 8 + 4];
            float4 b0 = *(const float4*)&Bs[k][tx * 4];
            float ar[8] = {a0.x, a0.y, a0.z, a0.w, a1.x, a1.y, a1.z, a1.w};
            float br[4] = {b0.x, b0.y, b0.z, b0.w};
            #pragma unroll
            for (int m = 0; m < 8; m++)
                #pragma unroll
                for (int n = 0; n < 4; n++)
                    acc[m][n] = fmaf(ar[m], br[n], acc[m][n]);
        }
        __syncthreads();
    }
    #pragma unroll
    for (int m = 0; m < 8; m++) {
        int row = bm + ty * 8 + m;
        if (row >= M) continue;
        #pragma unroll
        for (int n = 0; n < 4; n++) {
            int col = bn + tx * 4 + n;
            float v = acc[m][n];
            if (epi == 1) {
                v += bias[col];
                v = v > 0.f ? v : expm1f(v);
            }
            C[(size_t)row * N + col] = v;
        }
    }
}

// ---------------- fused masked-softmax attention + aggregation ----------------
// 8 exercise rows per block, 256 threads. Writes new_kc and new_kc*exEh into feat.
#define ROWS 8
#define NCH  8   // ceil(2000/256)
__global__ __launch_bounds__(256) void attn_kernel(
    const float* __restrict__ e1, const float* __restrict__ e2,
    const int* __restrict__ adj, const float* __restrict__ kcWh,
    const float* __restrict__ exEh, float* __restrict__ feat)
{
    __shared__ float e2s[N_KC];
    __shared__ unsigned maskb[ROWS][64];
    __shared__ float pbuf[ROWS][256];
    __shared__ float red[8];
    __shared__ float rmax_s[ROWS];
    __shared__ float rinv_s[ROWS];
    __shared__ float e1s[ROWS];

    int tid  = threadIdx.x;
    int lane = tid & 31;
    int warp = tid >> 5;
    int i0 = blockIdx.x * ROWS;

    for (int j = tid; j < N_KC; j += 256) e2s[j] = e2[j];
    if (tid < ROWS) e1s[tid] = e1[i0 + tid];
    __syncthreads();

    // ----- per-row softmax stats + adjacency bit-pack -----
    for (int i = 0; i < ROWS; i++) {
        float e1i = e1s[i];
        const int* arow = adj + (size_t)(i0 + i) * N_KC;
        float lmax = -INFINITY;
        #pragma unroll
        for (int it = 0; it < NCH; it++) {
            int j = tid + it * 256;
            int av = (j < N_KC) ? arow[j] : 0;
            unsigned bal = __ballot_sync(0xFFFFFFFFu, av > 0);
            if (lane == 0) maskb[i][warp + it * 8] = bal;
            if (av > 0) {
                float v = e1i + e2s[j];
                v = v > 0.f ? v : ALPHA * v;
                lmax = fmaxf(lmax, v);
            }
        }
        #pragma unroll
        for (int o = 16; o; o >>= 1) lmax = fmaxf(lmax, __shfl_xor_sync(0xFFFFFFFFu, lmax, o));
        if (lane == 0) red[warp] = lmax;
        __syncthreads();
        if (warp == 0) {
            float m = (lane < 8) ? red[lane] : -INFINITY;
            #pragma unroll
            for (int o = 4; o; o >>= 1) m = fmaxf(m, __shfl_xor_sync(0xFFFFFFFFu, m, o));
            if (lane == 0) red[0] = m;
        }
        __syncthreads();
        float rmax = red[0];
        __syncthreads();

        float lsum = 0.f;
        if (rmax > -INFINITY) {
            #pragma unroll
            for (int it = 0; it < NCH; it++) {
                int j = tid + it * 256;
                if (j < N_KC) {
                    unsigned bit = (maskb[i][j >> 5] >> (j & 31)) & 1u;
                    if (bit) {
                        float v = e1i + e2s[j];
                        v = v > 0.f ? v : ALPHA * v;
                        lsum += __expf(v - rmax);
                    }
                }
            }
        }
        #pragma unroll
        for (int o = 16; o; o >>= 1) lsum += __shfl_xor_sync(0xFFFFFFFFu, lsum, o);
        if (lane == 0) red[warp] = lsum;
        __syncthreads();
        if (warp == 0 && lane == 0) {
            float s = 0.f;
            for (int w = 0; w < 8; w++) s += red[w];
            rmax_s[i] = rmax;
            // degenerate row (no edges): reference softmax is uniform 1/N_KC
            rinv_s[i] = (rmax > -INFINITY) ? 1.0f / s : -1.0f;
        }
        __syncthreads();
    }

    // ----- aggregation: acc[i] = sum_j p_ij * kcWh[j, tid] -----
    float acc[ROWS];
    #pragma unroll
    for (int i = 0; i < ROWS; i++) acc[i] = 0.f;

    for (int c = 0; c < NCH; c++) {
        int j0 = c * 256;
        int j = j0 + tid;
        if (j < N_KC) {
            float e2j = e2s[j];
            #pragma unroll
            for (int i = 0; i < ROWS; i++) {
                float rinv = rinv_s[i];
                float p;
                if (rinv < 0.f) {
                    p = 1.0f / N_KC;
                } else {
                    unsigned bit = (maskb[i][j >> 5] >> (j & 31)) & 1u;
                    float v = e1s[i] + e2j;
                    v = v > 0.f ? v : ALPHA * v;
                    p = bit ? __expf(v - rmax_s[i]) * rinv : 0.f;
                }
                pbuf[i][tid] = p;
            }
        } else {
            #pragma unroll
            for (int i = 0; i < ROWS; i++) pbuf[i][tid] = 0.f;
        }
        __syncthreads();
        int lim = min(256, N_KC - j0);   // 256 or 208; both % 4 == 0
        for (int jj = 0; jj < lim; jj += 4) {
            float w0 = kcWh[(size_t)(j0 + jj + 0) * OUT_F + tid];
            float w1 = kcWh[(size_t)(j0 + jj + 1) * OUT_F + tid];
            float w2 = kcWh[(size_t)(j0 + jj + 2) * OUT_F + tid];
            float w3 = kcWh[(size_t)(j0 + jj + 3) * OUT_F + tid];
            #pragma unroll
            for (int i = 0; i < ROWS; i++) {
                float4 p4 = *(const float4*)&pbuf[i][jj];
                acc[i] = fmaf(p4.x, w0, acc[i]);
                acc[i] = fmaf(p4.y, w1, acc[i]);
                acc[i] = fmaf(p4.z, w2, acc[i]);
                acc[i] = fmaf(p4.w, w3, acc[i]);
            }
        }
        __syncthreads();
    }

    #pragma unroll
    for (int i = 0; i < ROWS; i++) {
        int gi = i0 + i;
        float nk = acc[i];
        feat[(size_t)gi * (2 * OUT_F) + tid]          = nk;
        feat[(size_t)gi * (2 * OUT_F) + OUT_F + tid]  = nk * exEh[(size_t)gi * OUT_F + tid];
    }
}

// ---------------- launch ----------------
extern "C" void kernel_launch(void* const* d_in, const int* in_sizes, int n_in,
                              void* d_out, int out_size)
{
    const float* ex   = (const float*)d_in[0];
    const float* kc   = (const float*)d_in[1];
    const int*   adj  = (const int*)d_in[2];
    const float* W1   = (const float*)d_in[3];
    const float* E    = (const float*)d_in[4];
    const float* a    = (const float*)d_in[5];
    const float* rd_w = (const float*)d_in[6];
    const float* rd_b = (const float*)d_in[7];
    float* out = (float*)d_out;

    float *kcWh, *exEh, *feat, *e1, *e2, *v1, *v2, *rdT;
    cudaGetSymbolAddress((void**)&kcWh, g_kcWh);
    cudaGetSymbolAddress((void**)&exEh, g_exEh);
    cudaGetSymbolAddress((void**)&feat, g_feat);
    cudaGetSymbolAddress((void**)&e1, g_e1);
    cudaGetSymbolAddress((void**)&e2, g_e2);
    cudaGetSymbolAddress((void**)&v1, g_v1);
    cudaGetSymbolAddress((void**)&v2, g_v2);
    cudaGetSymbolAddress((void**)&rdT, g_rdT);

    // 1. v1, v2, rd_w transpose
    prep_kernel<<<1 + (2 * OUT_F * OUT_F + 255) / 256, 256>>>(W1, a, rd_w);

    // 2. kc_Wh = kc_h @ W1   [2000,256]
    sgemm_kernel<<<dim3(OUT_F / GBN, (N_KC + GBM - 1) / GBM), 256>>>(
        kc, W1, kcWh, N_KC, OUT_F, IN_F, nullptr, 0);

    // 3. e1 = ex @ v1, e2 = kc @ v2
    rowdot_kernel<<<(N_E * 32 + 255) / 256, 256>>>(ex, v1, e1, N_E);
    rowdot_kernel<<<(N_KC * 32 + 255) / 256, 256>>>(kc, v2, e2, N_KC);

    // 4. ex_Eh = ex @ E   [10000,256]
    sgemm_kernel<<<dim3(OUT_F / GBN, (N_E + GBM - 1) / GBM), 256>>>(
        ex, E, exEh, N_E, OUT_F, IN_F, nullptr, 0);

    // 5. fused attention -> feat [10000, 512]
    attn_kernel<<<N_E / ROWS, 256>>>(e1, e2, adj, kcWh, exEh, feat);

    // 6. out = elu(feat @ rdT + rd_b)   [10000,256]
    sgemm_kernel<<<dim3(OUT_F / GBN, (N_E + GBM - 1) / GBM), 256>>>(
        feat, rdT, out, N_E, OUT_F, 2 * OUT_F, rd_b, 1);
}